// round 1
// baseline (speedup 1.0000x reference)
#include <cuda_runtime.h>
#include <math.h>
#include <stdint.h>

#define DIMX   1536
#define QKVD   4608
#define NHEADS 24
#define HDIM   64
#define BB     2
#define NXX    2048
#define NCC    256
#define NTOTAL 2304
#define ATT_SCALE 0.125f   // 64^-0.5

// Scratch (static device allocations — allowed; no cudaMalloc anywhere)
// layout [B, H, N, D]
__device__ float g_q[(size_t)BB*NHEADS*NTOTAL*HDIM];
__device__ float g_k[(size_t)BB*NHEADS*NTOTAL*HDIM];
__device__ float g_v[(size_t)BB*NHEADS*NTOTAL*HDIM];
__device__ float g_o[(size_t)BB*NHEADS*NTOTAL*HDIM];

// ---------------------------------------------------------------------------
// QKV GEMM:  C[M, 4608] = A[M,1536] @ W[4608,1536]^T + b, scattered to q/k/v.
// Tile 128x128x16, 256 threads, 8x8 per-thread microtile (two 4-wide spans).
// ---------------------------------------------------------------------------
__global__ __launch_bounds__(256) void qkv_kernel(
    const float* __restrict__ A, const float* __restrict__ W,
    const float* __restrict__ bias, int Nt, int n_off)
{
    __shared__ float As[16][128];
    __shared__ float Ws[16][128];
    const int tid = threadIdx.x;
    const int tx = tid & 15, ty = tid >> 4;
    const int rowBase = blockIdx.y * 128;
    const int colBase = blockIdx.x * 128;

    float acc[8][8];
#pragma unroll
    for (int i = 0; i < 8; i++)
#pragma unroll
        for (int j = 0; j < 8; j++) acc[i][j] = 0.f;

    for (int k0 = 0; k0 < DIMX; k0 += 16) {
#pragma unroll
        for (int i = 0; i < 2; i++) {
            int lin = tid + i * 256;         // 0..511 float4 slots
            int r   = lin >> 2;              // 0..127
            int kk  = (lin & 3) << 2;        // 0,4,8,12
            float4 va = *(const float4*)(A + (size_t)(rowBase + r) * DIMX + k0 + kk);
            As[kk + 0][r] = va.x; As[kk + 1][r] = va.y;
            As[kk + 2][r] = va.z; As[kk + 3][r] = va.w;
            float4 vw = *(const float4*)(W + (size_t)(colBase + r) * DIMX + k0 + kk);
            Ws[kk + 0][r] = vw.x; Ws[kk + 1][r] = vw.y;
            Ws[kk + 2][r] = vw.z; Ws[kk + 3][r] = vw.w;
        }
        __syncthreads();
#pragma unroll
        for (int kk = 0; kk < 16; kk++) {
            float a[8], w[8];
            *(float4*)&a[0] = *(float4*)&As[kk][ty * 4];
            *(float4*)&a[4] = *(float4*)&As[kk][64 + ty * 4];
            *(float4*)&w[0] = *(float4*)&Ws[kk][tx * 4];
            *(float4*)&w[4] = *(float4*)&Ws[kk][64 + tx * 4];
#pragma unroll
            for (int i = 0; i < 8; i++)
#pragma unroll
                for (int j = 0; j < 8; j++)
                    acc[i][j] += a[i] * w[j];
        }
        __syncthreads();
    }

    // Epilogue: add bias, scatter into q/k/v [B,H,N,D]
#pragma unroll
    for (int i = 0; i < 8; i++) {
        int r  = rowBase + ((i < 4) ? (ty * 4 + i) : (64 + ty * 4 + i - 4));
        int bi = r / Nt;
        int n  = r - bi * Nt;
#pragma unroll
        for (int j = 0; j < 8; j++) {
            int cidx = colBase + ((j < 4) ? (tx * 4 + j) : (64 + tx * 4 + j - 4));
            float vv = acc[i][j] + bias[cidx];
            int three = cidx / DIMX;
            int rem   = cidx - three * DIMX;
            int h = rem >> 6, d = rem & 63;
            float* dst = (three == 0) ? g_q : (three == 1) ? g_k : g_v;
            dst[(((size_t)bi * NHEADS + h) * NTOTAL + (n_off + n)) * HDIM + d] = vv;
        }
    }
}

// ---------------------------------------------------------------------------
// Flash attention: one thread = one query row. K/V streamed in 64-row tiles.
// grid = (NTOTAL/128, NHEADS, B), block = 128
// ---------------------------------------------------------------------------
__global__ __launch_bounds__(128) void attn_kernel()
{
    __shared__ float Ks[64][64];
    __shared__ float Vs[64][64];

    const int qrow = blockIdx.x * 128 + threadIdx.x;
    const int h  = blockIdx.y;
    const int bi = blockIdx.z;
    const size_t headbase = ((size_t)bi * NHEADS + h) * NTOTAL;

    float q[64], o[64];
    {
        const float4* qp = (const float4*)(g_q + (headbase + qrow) * HDIM);
#pragma unroll
        for (int i = 0; i < 16; i++) {
            float4 t = qp[i];
            q[4 * i + 0] = t.x; q[4 * i + 1] = t.y;
            q[4 * i + 2] = t.z; q[4 * i + 3] = t.w;
        }
    }
#pragma unroll
    for (int i = 0; i < 64; i++) o[i] = 0.f;

    float m = -1e30f, l = 0.f;

    for (int jt = 0; jt < NTOTAL; jt += 64) {
#pragma unroll
        for (int i = 0; i < 8; i++) {
            int lin = threadIdx.x + i * 128;   // 0..1023 float4 slots
            int r   = lin >> 4;                // 0..63
            int c4  = (lin & 15) << 2;         // 0..60
            *(float4*)&Ks[r][c4] = *(const float4*)(g_k + (headbase + jt + r) * HDIM + c4);
            *(float4*)&Vs[r][c4] = *(const float4*)(g_v + (headbase + jt + r) * HDIM + c4);
        }
        __syncthreads();

        for (int j = 0; j < 64; j++) {
            float s = 0.f;
#pragma unroll
            for (int d4 = 0; d4 < 16; d4++) {
                float4 kv = *(const float4*)&Ks[j][d4 * 4];
                s += q[d4 * 4 + 0] * kv.x + q[d4 * 4 + 1] * kv.y
                   + q[d4 * 4 + 2] * kv.z + q[d4 * 4 + 3] * kv.w;
            }
            s *= ATT_SCALE;
            if (s <= m) {
                float p = __expf(s - m);
                l += p;
#pragma unroll
                for (int d4 = 0; d4 < 16; d4++) {
                    float4 vv = *(const float4*)&Vs[j][d4 * 4];
                    o[d4 * 4 + 0] += p * vv.x; o[d4 * 4 + 1] += p * vv.y;
                    o[d4 * 4 + 2] += p * vv.z; o[d4 * 4 + 3] += p * vv.w;
                }
            } else {
                float corr = __expf(m - s);
                m = s;
                l = l * corr + 1.f;
#pragma unroll
                for (int d4 = 0; d4 < 16; d4++) {
                    float4 vv = *(const float4*)&Vs[j][d4 * 4];
                    o[d4 * 4 + 0] = o[d4 * 4 + 0] * corr + vv.x;
                    o[d4 * 4 + 1] = o[d4 * 4 + 1] * corr + vv.y;
                    o[d4 * 4 + 2] = o[d4 * 4 + 2] * corr + vv.z;
                    o[d4 * 4 + 3] = o[d4 * 4 + 3] * corr + vv.w;
                }
            }
        }
        __syncthreads();
    }

    const float inv = 1.f / l;
    float* op = g_o + (headbase + qrow) * HDIM;
#pragma unroll
    for (int d4 = 0; d4 < 16; d4++) {
        float4 t;
        t.x = o[d4 * 4 + 0] * inv; t.y = o[d4 * 4 + 1] * inv;
        t.z = o[d4 * 4 + 2] * inv; t.w = o[d4 * 4 + 3] * inv;
        *(float4*)(op + d4 * 4) = t;
    }
}

// ---------------------------------------------------------------------------
// Projection GEMM: out[M,1536] = Attn(B,N,H*D) @ Wp[1536,1536]^T + b
// A gathered from g_o [B,H,N,D] on the fly.
// ---------------------------------------------------------------------------
__global__ __launch_bounds__(256) void proj_kernel(
    const float* __restrict__ W, const float* __restrict__ bias,
    float* __restrict__ out, int Nt, int n_off)
{
    __shared__ float As[16][128];
    __shared__ float Ws[16][128];
    const int tid = threadIdx.x;
    const int tx = tid & 15, ty = tid >> 4;
    const int rowBase = blockIdx.y * 128;
    const int colBase = blockIdx.x * 128;

    float acc[8][8];
#pragma unroll
    for (int i = 0; i < 8; i++)
#pragma unroll
        for (int j = 0; j < 8; j++) acc[i][j] = 0.f;

    for (int k0 = 0; k0 < DIMX; k0 += 16) {
#pragma unroll
        for (int i = 0; i < 2; i++) {
            int lin = tid + i * 256;
            int r   = lin >> 2;
            int kk  = (lin & 3) << 2;
            int row = rowBase + r;
            int bi  = row / Nt;
            int n   = row - bi * Nt;
            int k   = k0 + kk;
            int hh  = k >> 6, dd = k & 63;
            float4 va = *(const float4*)(g_o +
                (((size_t)bi * NHEADS + hh) * NTOTAL + (n_off + n)) * HDIM + dd);
            As[kk + 0][r] = va.x; As[kk + 1][r] = va.y;
            As[kk + 2][r] = va.z; As[kk + 3][r] = va.w;
            float4 vw = *(const float4*)(W + (size_t)(colBase + r) * DIMX + k0 + kk);
            Ws[kk + 0][r] = vw.x; Ws[kk + 1][r] = vw.y;
            Ws[kk + 2][r] = vw.z; Ws[kk + 3][r] = vw.w;
        }
        __syncthreads();
#pragma unroll
        for (int kk = 0; kk < 16; kk++) {
            float a[8], w[8];
            *(float4*)&a[0] = *(float4*)&As[kk][ty * 4];
            *(float4*)&a[4] = *(float4*)&As[kk][64 + ty * 4];
            *(float4*)&w[0] = *(float4*)&Ws[kk][tx * 4];
            *(float4*)&w[4] = *(float4*)&Ws[kk][64 + tx * 4];
#pragma unroll
            for (int i = 0; i < 8; i++)
#pragma unroll
                for (int j = 0; j < 8; j++)
                    acc[i][j] += a[i] * w[j];
        }
        __syncthreads();
    }

#pragma unroll
    for (int i = 0; i < 8; i++) {
        int r = rowBase + ((i < 4) ? (ty * 4 + i) : (64 + ty * 4 + i - 4));
#pragma unroll
        for (int j = 0; j < 8; j++) {
            int cidx = colBase + ((j < 4) ? (tx * 4 + j) : (64 + tx * 4 + j - 4));
            out[(size_t)r * DIMX + cidx] = acc[i][j] + bias[cidx];
        }
    }
}

// ---------------------------------------------------------------------------
extern "C" void kernel_launch(void* const* d_in, const int* in_sizes, int n_in,
                              void* d_out, int out_size)
{
    const float* x       = (const float*)d_in[0];
    const float* c       = (const float*)d_in[1];
    const float* Wqkv_x  = (const float*)d_in[2];
    const float* bqkv_x  = (const float*)d_in[3];
    const float* Wqkv_c  = (const float*)d_in[4];
    const float* bqkv_c  = (const float*)d_in[5];
    const float* Wproj_x = (const float*)d_in[6];
    const float* bproj_x = (const float*)d_in[7];
    const float* Wproj_c = (const float*)d_in[8];
    const float* bproj_c = (const float*)d_in[9];
    float* out = (float*)d_out;

    // QKV projections (scatter into g_q/g_k/g_v [B,H,N,D])
    qkv_kernel<<<dim3(QKVD / 128, (BB * NXX) / 128), 256>>>(x, Wqkv_x, bqkv_x, NXX, 0);
    qkv_kernel<<<dim3(QKVD / 128, (BB * NCC) / 128), 256>>>(c, Wqkv_c, bqkv_c, NCC, NXX);

    // Joint attention over N = 2304
    attn_kernel<<<dim3(NTOTAL / 128, NHEADS, BB), 128>>>();

    // Output projections (x_out first, then c_out, concatenated in d_out)
    proj_kernel<<<dim3(DIMX / 128, (BB * NXX) / 128), 256>>>(
        Wproj_x, bproj_x, out, NXX, 0);
    proj_kernel<<<dim3(DIMX / 128, (BB * NCC) / 128), 256>>>(
        Wproj_c, bproj_c, out + (size_t)BB * NXX * DIMX, NCC, NXX);
}

// round 2
// speedup vs baseline: 3.2806x; 3.2806x over previous
#include <cuda_runtime.h>
#include <cstdint>
#include <math.h>

#define DIMX   1536
#define QKVD   4608
#define NHEADS 24
#define HDIM   64
#define BB     2
#define NXX    2048
#define NCC    256
#define NTOTAL 2304
#define ATT_SCALE 0.125f
#define SSTR   68    // padded stride for 64-wide attention tiles
#define GSTR   20    // padded stride for K=16 GEMM tiles

// Scratch [B,H,N,D]
__device__ float g_q[(size_t)BB*NHEADS*NTOTAL*HDIM];
__device__ float g_k[(size_t)BB*NHEADS*NTOTAL*HDIM];
__device__ float g_v[(size_t)BB*NHEADS*NTOTAL*HDIM];
__device__ float g_o[(size_t)BB*NHEADS*NTOTAL*HDIM];

__device__ __forceinline__ uint32_t f2tf(float x) {
    uint32_t u;
    asm("cvt.rna.tf32.f32 %0, %1;" : "=r"(u) : "f"(x));
    return u;
}

__device__ __forceinline__ void mma_tf32(float* d, const uint32_t* a, uint32_t b0, uint32_t b1) {
    asm volatile(
        "mma.sync.aligned.m16n8k8.row.col.f32.tf32.tf32.f32 "
        "{%0,%1,%2,%3}, {%4,%5,%6,%7}, {%8,%9}, {%0,%1,%2,%3};"
        : "+f"(d[0]), "+f"(d[1]), "+f"(d[2]), "+f"(d[3])
        : "r"(a[0]), "r"(a[1]), "r"(a[2]), "r"(a[3]), "r"(b0), "r"(b1));
}

// ---------------------------------------------------------------------------
// QKV GEMM (tf32 mma): C[M,4608] = A[M,1536] @ W^T + b, scatter to q/k/v
// block 256 thr = 8 warps (4x2), warp tile 32x64, block tile 128x128, Ktile 16
// ---------------------------------------------------------------------------
__global__ __launch_bounds__(256) void qkv_mma_kernel(
    const float* __restrict__ A, const float* __restrict__ W,
    const float* __restrict__ bias, int Nt, int n_off)
{
    __shared__ uint32_t As[128 * GSTR];
    __shared__ uint32_t Bs[128 * GSTR];
    const int tid = threadIdx.x;
    const int w = tid >> 5, lane = tid & 31;
    const int qg = lane >> 2, qt = lane & 3;
    const int mbase = (w & 3) * 32, nbase = (w >> 2) * 64;
    const int rowBase = blockIdx.y * 128;
    const int colBase = blockIdx.x * 128;

    float acc[2][8][4];
#pragma unroll
    for (int mf = 0; mf < 2; mf++)
#pragma unroll
        for (int nf = 0; nf < 8; nf++)
#pragma unroll
            for (int e = 0; e < 4; e++) acc[mf][nf][e] = 0.f;

    for (int k0 = 0; k0 < DIMX; k0 += 16) {
#pragma unroll
        for (int i = 0; i < 2; i++) {
            int lin = tid + i * 256;          // 0..511
            int r = lin >> 2, kk = (lin & 3) << 2;
            float4 va = *(const float4*)(A + (size_t)(rowBase + r) * DIMX + k0 + kk);
            uint32_t* da = &As[r * GSTR + kk];
            da[0] = f2tf(va.x); da[1] = f2tf(va.y); da[2] = f2tf(va.z); da[3] = f2tf(va.w);
            float4 vw = *(const float4*)(W + (size_t)(colBase + r) * DIMX + k0 + kk);
            uint32_t* db = &Bs[r * GSTR + kk];
            db[0] = f2tf(vw.x); db[1] = f2tf(vw.y); db[2] = f2tf(vw.z); db[3] = f2tf(vw.w);
        }
        __syncthreads();
#pragma unroll
        for (int kf = 0; kf < 2; kf++) {
            int kc = kf * 8;
            uint32_t a[2][4], b[8][2];
#pragma unroll
            for (int mf = 0; mf < 2; mf++) {
                int r = mbase + mf * 16;
                a[mf][0] = As[(r + qg) * GSTR + kc + qt];
                a[mf][1] = As[(r + qg + 8) * GSTR + kc + qt];
                a[mf][2] = As[(r + qg) * GSTR + kc + qt + 4];
                a[mf][3] = As[(r + qg + 8) * GSTR + kc + qt + 4];
            }
#pragma unroll
            for (int nf = 0; nf < 8; nf++) {
                int c = nbase + nf * 8;
                b[nf][0] = Bs[(c + qg) * GSTR + kc + qt];
                b[nf][1] = Bs[(c + qg) * GSTR + kc + qt + 4];
            }
#pragma unroll
            for (int mf = 0; mf < 2; mf++)
#pragma unroll
                for (int nf = 0; nf < 8; nf++)
                    mma_tf32(acc[mf][nf], a[mf], b[nf][0], b[nf][1]);
        }
        __syncthreads();
    }

    // scatter epilogue into q/k/v [B,H,N,D]
#pragma unroll
    for (int mf = 0; mf < 2; mf++) {
#pragma unroll
        for (int er = 0; er < 2; er++) {
            int r = rowBase + mbase + mf * 16 + qg + er * 8;
            int bi = r / Nt;
            int n = r - bi * Nt;
#pragma unroll
            for (int nf = 0; nf < 8; nf++) {
                int cidx = colBase + nbase + nf * 8 + 2 * qt;
                float v0 = acc[mf][nf][er * 2 + 0] + bias[cidx];
                float v1 = acc[mf][nf][er * 2 + 1] + bias[cidx + 1];
                int three = cidx / DIMX;
                int rem = cidx - three * DIMX;
                int h = rem >> 6, d = rem & 63;
                float* dst = (three == 0) ? g_q : (three == 1) ? g_k : g_v;
                *(float2*)(dst + (((size_t)bi * NHEADS + h) * NTOTAL + (n_off + n)) * HDIM + d)
                    = make_float2(v0, v1);
            }
        }
    }
}

// ---------------------------------------------------------------------------
// Flash attention (tf32 mma). Block = 64 queries x (b,h). 4 warps, each owns
// 16 full query rows. Bc = 64. P staged through smem (reuses Q buffer).
// ---------------------------------------------------------------------------
__global__ __launch_bounds__(128) void attn_mma_kernel()
{
    __shared__ uint32_t Ks[64 * SSTR];
    __shared__ uint32_t Vs[64 * SSTR];
    __shared__ uint32_t Qs[64 * SSTR];   // becomes Ps after Q frags extracted

    const int tid = threadIdx.x;
    const int w = tid >> 5, lane = tid & 31;
    const int qg = lane >> 2, qt = lane & 3;
    const int h = blockIdx.y, bi = blockIdx.z;
    const size_t headbase = ((size_t)bi * NHEADS + h) * NTOTAL;
    const int qbase = blockIdx.x * 64;
    const int mrow = w * 16;

    // stage Q (tf32)
#pragma unroll
    for (int i = 0; i < 8; i++) {
        int lin = tid + i * 128;          // 0..1023 float4 slots
        int r = lin >> 4, c4 = (lin & 15) << 2;
        float4 t = *(const float4*)(g_q + (headbase + qbase + r) * HDIM + c4);
        uint32_t* d = &Qs[r * SSTR + c4];
        d[0] = f2tf(t.x); d[1] = f2tf(t.y); d[2] = f2tf(t.z); d[3] = f2tf(t.w);
    }
    __syncthreads();

    uint32_t qf[8][4];
#pragma unroll
    for (int kf = 0; kf < 8; kf++) {
        int kc = kf * 8;
        qf[kf][0] = Qs[(mrow + qg) * SSTR + kc + qt];
        qf[kf][1] = Qs[(mrow + qg + 8) * SSTR + kc + qt];
        qf[kf][2] = Qs[(mrow + qg) * SSTR + kc + qt + 4];
        qf[kf][3] = Qs[(mrow + qg + 8) * SSTR + kc + qt + 4];
    }
    __syncthreads();
    uint32_t* Ps = Qs;

    float of[8][4];
#pragma unroll
    for (int nf = 0; nf < 8; nf++)
#pragma unroll
        for (int e = 0; e < 4; e++) of[nf][e] = 0.f;
    float m0 = -1e30f, m1 = -1e30f, l0 = 0.f, l1 = 0.f;

    for (int jt = 0; jt < NTOTAL; jt += 64) {
#pragma unroll
        for (int i = 0; i < 8; i++) {
            int lin = tid + i * 128;
            int r = lin >> 4, c4 = (lin & 15) << 2;
            float4 tk = *(const float4*)(g_k + (headbase + jt + r) * HDIM + c4);
            float4 tv = *(const float4*)(g_v + (headbase + jt + r) * HDIM + c4);
            uint32_t* dk = &Ks[r * SSTR + c4];
            dk[0] = f2tf(tk.x); dk[1] = f2tf(tk.y); dk[2] = f2tf(tk.z); dk[3] = f2tf(tk.w);
            uint32_t* dv = &Vs[r * SSTR + c4];
            dv[0] = f2tf(tv.x); dv[1] = f2tf(tv.y); dv[2] = f2tf(tv.z); dv[3] = f2tf(tv.w);
        }
        __syncthreads();

        // S = Q K^T  (warp: 16 x 64)
        float sf[8][4];
#pragma unroll
        for (int nf = 0; nf < 8; nf++)
#pragma unroll
            for (int e = 0; e < 4; e++) sf[nf][e] = 0.f;
#pragma unroll
        for (int kf = 0; kf < 8; kf++) {
            int kc = kf * 8;
#pragma unroll
            for (int nf = 0; nf < 8; nf++) {
                uint32_t b0 = Ks[(nf * 8 + qg) * SSTR + kc + qt];
                uint32_t b1 = Ks[(nf * 8 + qg) * SSTR + kc + qt + 4];
                mma_tf32(sf[nf], qf[kf], b0, b1);
            }
        }

        // online softmax over the 64 cols (rows fully within this warp)
        float mx0 = -1e30f, mx1 = -1e30f;
#pragma unroll
        for (int nf = 0; nf < 8; nf++) {
            sf[nf][0] *= ATT_SCALE; sf[nf][1] *= ATT_SCALE;
            sf[nf][2] *= ATT_SCALE; sf[nf][3] *= ATT_SCALE;
            mx0 = fmaxf(mx0, fmaxf(sf[nf][0], sf[nf][1]));
            mx1 = fmaxf(mx1, fmaxf(sf[nf][2], sf[nf][3]));
        }
        mx0 = fmaxf(mx0, __shfl_xor_sync(0xffffffffu, mx0, 1));
        mx0 = fmaxf(mx0, __shfl_xor_sync(0xffffffffu, mx0, 2));
        mx1 = fmaxf(mx1, __shfl_xor_sync(0xffffffffu, mx1, 1));
        mx1 = fmaxf(mx1, __shfl_xor_sync(0xffffffffu, mx1, 2));

        float nm0 = fmaxf(m0, mx0), nm1 = fmaxf(m1, mx1);
        float corr0 = __expf(m0 - nm0), corr1 = __expf(m1 - nm1);
        float s0 = 0.f, s1 = 0.f;
#pragma unroll
        for (int nf = 0; nf < 8; nf++) {
            float p00 = __expf(sf[nf][0] - nm0);
            float p01 = __expf(sf[nf][1] - nm0);
            float p10 = __expf(sf[nf][2] - nm1);
            float p11 = __expf(sf[nf][3] - nm1);
            s0 += p00 + p01; s1 += p10 + p11;
            int col = nf * 8 + 2 * qt;
            Ps[(mrow + qg) * SSTR + col]     = f2tf(p00);
            Ps[(mrow + qg) * SSTR + col + 1] = f2tf(p01);
            Ps[(mrow + qg + 8) * SSTR + col]     = f2tf(p10);
            Ps[(mrow + qg + 8) * SSTR + col + 1] = f2tf(p11);
            of[nf][0] *= corr0; of[nf][1] *= corr0;
            of[nf][2] *= corr1; of[nf][3] *= corr1;
        }
        s0 += __shfl_xor_sync(0xffffffffu, s0, 1);
        s0 += __shfl_xor_sync(0xffffffffu, s0, 2);
        s1 += __shfl_xor_sync(0xffffffffu, s1, 1);
        s1 += __shfl_xor_sync(0xffffffffu, s1, 2);
        l0 = l0 * corr0 + s0; l1 = l1 * corr1 + s1;
        m0 = nm0; m1 = nm1;
        __syncwarp();

        // O += P @ V
#pragma unroll
        for (int kf = 0; kf < 8; kf++) {
            int jc = kf * 8;
            uint32_t a[4];
            a[0] = Ps[(mrow + qg) * SSTR + jc + qt];
            a[1] = Ps[(mrow + qg + 8) * SSTR + jc + qt];
            a[2] = Ps[(mrow + qg) * SSTR + jc + qt + 4];
            a[3] = Ps[(mrow + qg + 8) * SSTR + jc + qt + 4];
#pragma unroll
            for (int nf = 0; nf < 8; nf++) {
                uint32_t b0 = Vs[(jc + qt) * SSTR + nf * 8 + qg];
                uint32_t b1 = Vs[(jc + qt + 4) * SSTR + nf * 8 + qg];
                mma_tf32(of[nf], a, b0, b1);
            }
        }
        __syncthreads();
    }

    const float inv0 = 1.f / l0, inv1 = 1.f / l1;
    const int row0 = qbase + mrow + qg, row1 = row0 + 8;
#pragma unroll
    for (int nf = 0; nf < 8; nf++) {
        int col = nf * 8 + 2 * qt;
        *(float2*)(g_o + (headbase + row0) * HDIM + col)
            = make_float2(of[nf][0] * inv0, of[nf][1] * inv0);
        *(float2*)(g_o + (headbase + row1) * HDIM + col)
            = make_float2(of[nf][2] * inv1, of[nf][3] * inv1);
    }
}

// ---------------------------------------------------------------------------
// Projection GEMM (tf32 mma), A gathered from g_o [B,H,N,D]
// ---------------------------------------------------------------------------
__global__ __launch_bounds__(256) void proj_mma_kernel(
    const float* __restrict__ W, const float* __restrict__ bias,
    float* __restrict__ out, int Nt, int n_off)
{
    __shared__ uint32_t As[128 * GSTR];
    __shared__ uint32_t Bs[128 * GSTR];
    const int tid = threadIdx.x;
    const int w = tid >> 5, lane = tid & 31;
    const int qg = lane >> 2, qt = lane & 3;
    const int mbase = (w & 3) * 32, nbase = (w >> 2) * 64;
    const int rowBase = blockIdx.y * 128;
    const int colBase = blockIdx.x * 128;

    float acc[2][8][4];
#pragma unroll
    for (int mf = 0; mf < 2; mf++)
#pragma unroll
        for (int nf = 0; nf < 8; nf++)
#pragma unroll
            for (int e = 0; e < 4; e++) acc[mf][nf][e] = 0.f;

    for (int k0 = 0; k0 < DIMX; k0 += 16) {
#pragma unroll
        for (int i = 0; i < 2; i++) {
            int lin = tid + i * 256;
            int r = lin >> 2, kk = (lin & 3) << 2;
            int row = rowBase + r;
            int bi = row / Nt;
            int n = row - bi * Nt;
            int k = k0 + kk;
            int hh = k >> 6, dd = k & 63;
            float4 va = *(const float4*)(g_o +
                (((size_t)bi * NHEADS + hh) * NTOTAL + (n_off + n)) * HDIM + dd);
            uint32_t* da = &As[r * GSTR + kk];
            da[0] = f2tf(va.x); da[1] = f2tf(va.y); da[2] = f2tf(va.z); da[3] = f2tf(va.w);
            float4 vw = *(const float4*)(W + (size_t)(colBase + r) * DIMX + k0 + kk);
            uint32_t* db = &Bs[r * GSTR + kk];
            db[0] = f2tf(vw.x); db[1] = f2tf(vw.y); db[2] = f2tf(vw.z); db[3] = f2tf(vw.w);
        }
        __syncthreads();
#pragma unroll
        for (int kf = 0; kf < 2; kf++) {
            int kc = kf * 8;
            uint32_t a[2][4], b[8][2];
#pragma unroll
            for (int mf = 0; mf < 2; mf++) {
                int r = mbase + mf * 16;
                a[mf][0] = As[(r + qg) * GSTR + kc + qt];
                a[mf][1] = As[(r + qg + 8) * GSTR + kc + qt];
                a[mf][2] = As[(r + qg) * GSTR + kc + qt + 4];
                a[mf][3] = As[(r + qg + 8) * GSTR + kc + qt + 4];
            }
#pragma unroll
            for (int nf = 0; nf < 8; nf++) {
                int c = nbase + nf * 8;
                b[nf][0] = Bs[(c + qg) * GSTR + kc + qt];
                b[nf][1] = Bs[(c + qg) * GSTR + kc + qt + 4];
            }
#pragma unroll
            for (int mf = 0; mf < 2; mf++)
#pragma unroll
                for (int nf = 0; nf < 8; nf++)
                    mma_tf32(acc[mf][nf], a[mf], b[nf][0], b[nf][1]);
        }
        __syncthreads();
    }

#pragma unroll
    for (int mf = 0; mf < 2; mf++) {
#pragma unroll
        for (int er = 0; er < 2; er++) {
            int r = rowBase + mbase + mf * 16 + qg + er * 8;
#pragma unroll
            for (int nf = 0; nf < 8; nf++) {
                int cidx = colBase + nbase + nf * 8 + 2 * qt;
                float v0 = acc[mf][nf][er * 2 + 0] + bias[cidx];
                float v1 = acc[mf][nf][er * 2 + 1] + bias[cidx + 1];
                *(float2*)(out + (size_t)r * DIMX + cidx) = make_float2(v0, v1);
            }
        }
    }
}

// ---------------------------------------------------------------------------
extern "C" void kernel_launch(void* const* d_in, const int* in_sizes, int n_in,
                              void* d_out, int out_size)
{
    const float* x       = (const float*)d_in[0];
    const float* c       = (const float*)d_in[1];
    const float* Wqkv_x  = (const float*)d_in[2];
    const float* bqkv_x  = (const float*)d_in[3];
    const float* Wqkv_c  = (const float*)d_in[4];
    const float* bqkv_c  = (const float*)d_in[5];
    const float* Wproj_x = (const float*)d_in[6];
    const float* bproj_x = (const float*)d_in[7];
    const float* Wproj_c = (const float*)d_in[8];
    const float* bproj_c = (const float*)d_in[9];
    float* out = (float*)d_out;

    qkv_mma_kernel<<<dim3(QKVD / 128, (BB * NXX) / 128), 256>>>(x, Wqkv_x, bqkv_x, NXX, 0);
    qkv_mma_kernel<<<dim3(QKVD / 128, (BB * NCC) / 128), 256>>>(c, Wqkv_c, bqkv_c, NCC, NXX);

    attn_mma_kernel<<<dim3(NTOTAL / 64, NHEADS, BB), 128>>>();

    proj_mma_kernel<<<dim3(DIMX / 128, (BB * NXX) / 128), 256>>>(
        Wproj_x, bproj_x, out, NXX, 0);
    proj_mma_kernel<<<dim3(DIMX / 128, (BB * NCC) / 128), 256>>>(
        Wproj_c, bproj_c, out + (size_t)BB * NXX * DIMX, NCC, NXX);
}